// round 10
// baseline (speedup 1.0000x reference)
#include <cuda_runtime.h>
#include <cuda_bf16.h>
#include <math.h>

// Problem constants (fixed by the reference)
#define GROUPS 8
#define DG     32        // D / GROUPS
#define W_DIM  512
#define D_DIM  256
#define KCOEF  9         // CHEB_DEG + 1
#define RANK   16
#define DT_C   0.1f
#define XS     516       // xn row stride in floats (XS mod 32 == 4)
#define MS     36        // M row stride in floats (float4 access, conflict-free)
#define FULL   0xffffffffu
#define NTHR   512       // 16 warps; 2 blocks/SM (64 regs * 512 * 2 = full RF)

// Slab layout:  addr(c, w) = c*XS + 4*((l + 32*j4) ^ (c>>2)) + (w&3)
//   where l = w>>4 (owning lane in Phase B), j4 = (w>>2)&3.
// Conflict-free for: Phase A transposed scalar stores, Phase B per-lane
// contiguous float4 loads/stores, Phase C uniform broadcast reads.

// Precomputed per-group integration matrix M_g = (I + dt A + 0.5 dt^2 A^2)^4
__device__ float d_M[GROUPS * DG * DG];

// ---------------------------------------------------------------------------
// Precompute kernel: one block per group, 1024 threads (i = tid>>5, j = tid&31)
// ---------------------------------------------------------------------------
__global__ void precompute_M_kernel(const float* __restrict__ U,
                                    const float* __restrict__ V,
                                    const float* __restrict__ S) {
    const int g   = blockIdx.x;
    const int tid = threadIdx.x;
    const int i   = tid >> 5;
    const int j   = tid & 31;

    __shared__ float Us[DG * RANK], Vs[DG * RANK], Ss[DG * RANK];
    __shared__ float A[DG * 33], P[DG * 33], Q[DG * 33];
    __shared__ float trR_sh;

    if (tid < DG * RANK) {
        Us[tid] = U[g * DG * RANK + tid];
        Vs[tid] = V[g * DG * RANK + tid];
        Ss[tid] = S[g * DG * RANK + tid];
    }
    __syncthreads();

    if (tid < 32) {
        float s = 0.f;
        #pragma unroll
        for (int r = 0; r < RANK; ++r) {
            float v = Ss[tid * RANK + r];
            s = fmaf(v, v, s);
        }
        #pragma unroll
        for (int off = 16; off; off >>= 1)
            s += __shfl_xor_sync(FULL, s, off);
        if (tid == 0) trR_sh = s;
    }
    __syncthreads();

    {
        float a = 0.f;
        #pragma unroll
        for (int r = 0; r < RANK; ++r) {
            a = fmaf(Us[i * RANK + r],  Vs[j * RANK + r], a);
            a = fmaf(-Vs[i * RANK + r], Us[j * RANK + r], a);
            a = fmaf(-Ss[i * RANK + r], Ss[j * RANK + r], a);
        }
        if (i == j) a += trR_sh / (float)DG;
        A[i * 33 + j] = a;
    }
    __syncthreads();

    {
        float a2 = 0.f;
        #pragma unroll
        for (int k = 0; k < DG; ++k)
            a2 = fmaf(A[i * 33 + k], A[k * 33 + j], a2);
        float p = DT_C * A[i * 33 + j] + 0.5f * DT_C * DT_C * a2;
        if (i == j) p += 1.0f;
        P[i * 33 + j] = p;
    }
    __syncthreads();

    {
        float q = 0.f;
        #pragma unroll
        for (int k = 0; k < DG; ++k)
            q = fmaf(P[i * 33 + k], P[k * 33 + j], q);
        Q[i * 33 + j] = q;
    }
    __syncthreads();

    {
        float m = 0.f;
        #pragma unroll
        for (int k = 0; k < DG; ++k)
            m = fmaf(Q[i * 33 + k], Q[k * 33 + j], m);
        d_M[g * DG * DG + i * DG + j] = m;
    }
}

// ---------------------------------------------------------------------------
// float4 helpers
// ---------------------------------------------------------------------------
__device__ __forceinline__ float4 f4_fma(float a, const float4 v, const float4 acc) {
    return make_float4(fmaf(a, v.x, acc.x), fmaf(a, v.y, acc.y),
                       fmaf(a, v.z, acc.z), fmaf(a, v.w, acc.w));
}
__device__ __forceinline__ float4 f4_negsub(const float4 s, const float4 t) {
    return make_float4(-s.x - t.x, -s.y - t.y, -s.z - t.z, -s.w - t.w);
}

// Neighbor sums for the path-Laplacian stencil. Each lane holds 16 CONTIGUOUS
// tokens w = 16*lane + j (t[4] float4s). Only 2 shuffles per application;
// Dirichlet zeros at w=0 and w=511.
__device__ __forceinline__ void nbr_sum16(const float4 (&t)[4], float4 (&s)[4], int lane) {
    float tl = __shfl_sync(FULL, t[3].w, (lane + 31) & 31);  // lane-1's last
    float tr = __shfl_sync(FULL, t[0].x, (lane + 1) & 31);   // lane+1's first
    if (lane == 0)  tl = 0.f;
    if (lane == 31) tr = 0.f;
    #pragma unroll
    for (int i = 0; i < 4; ++i) {
        s[i].x = (i > 0 ? t[i - 1].w : tl) + t[i].y;
        s[i].y = t[i].x + t[i].z;
        s[i].z = t[i].y + t[i].w;
        s[i].w = t[i].z + (i < 3 ? t[i + 1].x : tr);
    }
}

// One Chebyshev recurrence step: tp := -(left+right)(tc) - tp ;  y += ck*tp
__device__ __forceinline__ void cheb_step16(float4 (&tp)[4], const float4 (&tc)[4],
                                            float4 (&y)[4], float ck, int lane) {
    float4 s[4];
    nbr_sum16(tc, s, lane);
    #pragma unroll
    for (int i = 0; i < 4; ++i) {
        tp[i] = f4_negsub(s[i], tp[i]);
        y[i]  = f4_fma(ck, tp[i], y[i]);
    }
}

// ---------------------------------------------------------------------------
// Fused kernel: norm -> Chebyshev -> matvec(M_g).  Block = (b, g), 512 thr.
// 2 blocks resident per SM so one block's L1-heavy phases (A/C) overlap the
// other's shuffle/FMA phase (B).
// ---------------------------------------------------------------------------
__global__ __launch_bounds__(NTHR, 2)
void continuous_block_kernel(const float* __restrict__ x,
                             const float* __restrict__ cheb,
                             float* __restrict__ out) {
    extern __shared__ float sm[];
    float* xn  = sm;                    // [32][XS] channel-major swizzled slab
    float* Msm = sm + DG * XS;          // [32][MS]
    float* csm = Msm + DG * MS;         // [KCOEF]

    const int g    = blockIdx.x & (GROUPS - 1);
    const int b    = blockIdx.x >> 3;
    const int tid  = threadIdx.x;
    const int warp = tid >> 5;          // 0..15
    const int lane = tid & 31;

    // Stage M with float4: 16 warps x (2 rows, lanes 0..7 cover 8 quads/row).
    {
        const int r0 = warp;            // rows warp and warp+16
        if (lane < 8) {
            float4 m0 = *reinterpret_cast<const float4*>(
                            &d_M[g * DG * DG + r0 * DG + lane * 4]);
            *reinterpret_cast<float4*>(&Msm[r0 * MS + lane * 4]) = m0;
        } else if (lane < 16) {
            const int l = lane - 8;
            float4 m1 = *reinterpret_cast<const float4*>(
                            &d_M[g * DG * DG + (r0 + 16) * DG + l * 4]);
            *reinterpret_cast<float4*>(&Msm[(r0 + 16) * MS + l * 4]) = m1;
        }
    }
    if (tid < KCOEF) csm[tid] = cheb[g * KCOEF + tid];

    const size_t base = ((size_t)b * W_DIM) * D_DIM + (size_t)g * DG;

    // ---------------- Phase A: load + groupwise norm ------------------------
    // lane = 8*tg + c4 : tg = token-in-quad (w&3), c4 = channel quad.
    // Each warp handles two 16-token segments (warp2 = warp, warp+16).
    {
        const int tg = lane >> 3;
        const int c4 = lane & 7;
        #pragma unroll 1
        for (int ws = 0; ws < 2; ++ws) {
            const int warp2 = warp + 16 * ws;
            const int wb    = warp2 * 16;
            float4 v[4];
            #pragma unroll
            for (int tb = 0; tb < 4; ++tb) {
                const int w = wb + tb * 4 + tg;
                v[tb] = *reinterpret_cast<const float4*>(
                            &x[base + (size_t)w * D_DIM + c4 * 4]);
            }
            #pragma unroll
            for (int tb = 0; tb < 4; ++tb) {
                float s  = v[tb].x + v[tb].y + v[tb].z + v[tb].w;
                float s2 = fmaf(v[tb].x, v[tb].x, fmaf(v[tb].y, v[tb].y,
                           fmaf(v[tb].z, v[tb].z, v[tb].w * v[tb].w)));
                #pragma unroll
                for (int off = 4; off; off >>= 1) {   // within 8-lane group
                    s  += __shfl_xor_sync(FULL, s,  off);
                    s2 += __shfl_xor_sync(FULL, s2, off);
                }
                const float mu  = s * (1.0f / DG);
                const float var = fmaf(s2, 1.0f / DG, -mu * mu);
                const float inv = rsqrtf(var + 1e-6f);
                const float nx = (v[tb].x - mu) * inv;
                const float ny = (v[tb].y - mu) * inv;
                const float nz = (v[tb].z - mu) * inv;
                const float nw = (v[tb].w - mu) * inv;
                // slot = (l + 32*j4) ^ (c>>2): l = warp2, j4 = tb, c>>2 = c4
                const int off4 = 4 * ((warp2 + 32 * tb) ^ c4) + tg;
                xn[(4 * c4 + 0) * XS + off4] = nx;
                xn[(4 * c4 + 1) * XS + off4] = ny;
                xn[(4 * c4 + 2) * XS + off4] = nz;
                xn[(4 * c4 + 3) * XS + off4] = nw;
            }
        }
    }
    __syncthreads();

    // ---------------- Phase B: Chebyshev along W (2 sequential channels) ----
    // Lane holds 16 contiguous tokens w = 16*lane .. 16*lane+15.
    #pragma unroll 1
    for (int cp = 0; cp < 2; ++cp) {
        const int c  = warp + 16 * cp;
        const int sc = c >> 2;          // swizzle key
        float4 t0[4], t1[4], y[4];
        #pragma unroll
        for (int i = 0; i < 4; ++i)
            t0[i] = *reinterpret_cast<const float4*>(
                        &xn[c * XS + 4 * ((lane + 32 * i) ^ sc)]);

        {
            float4 s[4];
            nbr_sum16(t0, s, lane);
            const float c0 = csm[0], c1 = csm[1];
            #pragma unroll
            for (int i = 0; i < 4; ++i) {
                t1[i] = make_float4(-0.5f * s[i].x, -0.5f * s[i].y,
                                    -0.5f * s[i].z, -0.5f * s[i].w);
                y[i]  = make_float4(fmaf(c1, t1[i].x, c0 * t0[i].x),
                                    fmaf(c1, t1[i].y, c0 * t0[i].y),
                                    fmaf(c1, t1[i].z, c0 * t0[i].z),
                                    fmaf(c1, t1[i].w, c0 * t0[i].w));
            }
        }
        cheb_step16(t0, t1, y, csm[2], lane);   // T2
        cheb_step16(t1, t0, y, csm[3], lane);   // T3
        cheb_step16(t0, t1, y, csm[4], lane);   // T4
        cheb_step16(t1, t0, y, csm[5], lane);   // T5
        cheb_step16(t0, t1, y, csm[6], lane);   // T6
        cheb_step16(t1, t0, y, csm[7], lane);   // T7
        cheb_step16(t0, t1, y, csm[8], lane);   // T8

        #pragma unroll
        for (int i = 0; i < 4; ++i)
            *reinterpret_cast<float4*>(
                &xn[c * XS + 4 * ((lane + 32 * i) ^ sc)]) = y[i];
    }
    __syncthreads();

    // ---------------- Phase C: z = M_g * y ; lane = out channel ------------
    float Mreg[DG];
    #pragma unroll
    for (int k8 = 0; k8 < 8; ++k8) {
        // float4, bank-group 9*lane mod 8 -> conflict-free
        float4 m = *reinterpret_cast<const float4*>(&Msm[lane * MS + k8 * 4]);
        Mreg[4 * k8 + 0] = m.x;  Mreg[4 * k8 + 1] = m.y;
        Mreg[4 * k8 + 2] = m.z;  Mreg[4 * k8 + 3] = m.w;
    }

    #pragma unroll 1
    for (int ws = 0; ws < 2; ++ws) {
        const int warp2 = warp + 16 * ws;
        const int wb    = warp2 * 16;
        #pragma unroll
        for (int tb = 0; tb < 4; ++tb) {
            const int w0 = wb + tb * 4;     // l = warp2, j4 = tb
            float zx = 0.f, zy = 0.f, zz = 0.f, zw = 0.f;
            #pragma unroll
            for (int k = 0; k < DG; ++k) {
                // uniform address -> broadcast LDS.128 serving 4 tokens
                float4 yv = *reinterpret_cast<const float4*>(
                                &xn[k * XS + 4 * ((warp2 + 32 * tb) ^ (k >> 2))]);
                zx = fmaf(Mreg[k], yv.x, zx);
                zy = fmaf(Mreg[k], yv.y, zy);
                zz = fmaf(Mreg[k], yv.z, zz);
                zw = fmaf(Mreg[k], yv.w, zw);
            }
            float* o = &out[base + (size_t)w0 * D_DIM + lane];
            o[0 * D_DIM] = zx;
            o[1 * D_DIM] = zy;
            o[2 * D_DIM] = zz;
            o[3 * D_DIM] = zw;
        }
    }
}

// ---------------------------------------------------------------------------
extern "C" void kernel_launch(void* const* d_in, const int* in_sizes, int n_in,
                              void* d_out, int out_size) {
    const float* x    = (const float*)d_in[0];
    const float* cheb = (const float*)d_in[1];
    const float* U    = (const float*)d_in[2];
    const float* V    = (const float*)d_in[3];
    const float* S    = (const float*)d_in[4];
    float* out = (float*)d_out;

    const int B = in_sizes[0] / (W_DIM * D_DIM);

    const size_t smem = (DG * XS + DG * MS + 16) * sizeof(float);  // ~70.8 KB
    cudaFuncSetAttribute(continuous_block_kernel,
                         cudaFuncAttributeMaxDynamicSharedMemorySize, (int)smem);

    precompute_M_kernel<<<GROUPS, 1024>>>(U, V, S);
    continuous_block_kernel<<<B * GROUPS, NTHR, smem>>>(x, cheb, out);
}